// round 15
// baseline (speedup 1.0000x reference)
#include <cuda_runtime.h>
#include <cstdint>

typedef unsigned long long u64;
typedef unsigned int u32;

#define NB    64
#define CIN   256
#define HH    56
#define WW    56
#define HW    3136
#define NPIX  200704   // NB*HW
#define NQUAD 50176    // NPIX/4
#define NWRD  6272     // NPIX/32
#define CNTD  200704.0
#define EPSD  1e-5
#define PADW  58
#define PADHW 3364     // 58*58

// ---------------- static device scratch ----------------
__device__ u64  g_w1b[64 * 4];
__device__ u64  g_w2b[64 * 9];
__device__ u64  g_w3b[256];
__device__ int  g_ctab[9 * 64];       // border-pattern corrections for conv2
__device__ int4 g_s1v[8 * NPIX];      // conv1 outputs int16, [group][pixel]
__device__ short g_s2[NPIX * 64];     // conv2 outputs int16, [pixel][ch]
__device__ u64  g_a1p[NB * PADHW];    // conv2 input bits, zero halo
__device__ ulonglong4 g_a2[NQUAD];    // conv3 input bits (pixel-major u64)
__device__ u32  g_t3[NWRD * 64];      // transposed conv3 input bits: [pixword][bit]
__device__ int  g_G[4096];            // gram xor-popc, upper triangle i<j
__device__ int  g_n3[64];             // per-bit set counts
__device__ long long g_sum1[64], g_ss1[64];
__device__ long long g_sum2[64], g_ss2[64];
__device__ float g_A3[256], g_B3[256];   // FOLDED: A2 = -2A, B2 = 64A + B

// ---------------- K0: multi-block init; block b owns conv2-channel b ----------------
__global__ __launch_bounds__(64) void k0_init(const float* __restrict__ w1,
                                              const float* __restrict__ w2,
                                              const float* __restrict__ w3) {
    __shared__ float w2s[576];
    __shared__ u64 w2bits[9];
    const int b = blockIdx.x;    // 64 blocks
    const int t = threadIdx.x;   // 64 threads

    for (int i = t; i < 576; i += 64) w2s[i] = w2[b * 576 + i];

    if (t < 4) {
        u64 wd = 0;
        const float* wp = w1 + b * 256 + t * 64;
        #pragma unroll 8
        for (int c = 0; c < 64; c++) wd |= (u64)(wp[c] > 0.f) << c;
        g_w1b[b * 4 + t] = wd;
    }
    if (t >= 4 && t < 8) {
        const int ch = b * 4 + (t - 4);
        u64 wd = 0;
        const float* wp = w3 + ch * 64;
        #pragma unroll 8
        for (int c = 0; c < 64; c++) wd |= (u64)(wp[c] > 0.f) << c;
        g_w3b[ch] = wd;
    }
    g_G[b * 64 + t] = 0;
    if (b == 0) {
        g_sum1[t] = 0; g_ss1[t] = 0;
        g_sum2[t] = 0; g_ss2[t] = 0;
        g_n3[t] = 0;
    }
    __syncthreads();

    if (t < 9) {
        u64 wd = 0;
        #pragma unroll 8
        for (int ci = 0; ci < 64; ci++)
            wd |= (u64)(w2s[ci * 9 + t] > 0.f) << ci;
        g_w2b[b * 9 + t] = wd;
        w2bits[t] = wd;
    }
    __syncthreads();

    if (t < 9) {
        const int rowc = t / 3, colc = t - rowc * 3;
        int corr = 0;
        #pragma unroll
        for (int tap = 0; tap < 9; tap++) {
            const int r = tap / 3, c = tap - r * 3;
            bool inval = (rowc == 1 && r == 0) || (rowc == 2 && r == 2) ||
                         (colc == 1 && c == 0) || (colc == 2 && c == 2);
            if (inval) corr += 64 - 2 * __popcll(w2bits[tap]);
        }
        g_ctab[t * 64 + b] = corr;
    }
}

// ---------------- K1: conv1, warp-synchronous (no phase barrier) ----------------
__global__ __launch_bounds__(128) void k1_conv1(const float* __restrict__ x) {
    __shared__ u64 w1s[256];
    __shared__ int ssum[64], sss[64];
    const int tid = threadIdx.x;
    if (tid < 64) { ssum[tid] = 0; sss[tid] = 0; }
    w1s[tid] = g_w1b[tid];
    w1s[tid + 128] = g_w1b[tid + 128];
    __syncthreads();   // only barrier: w1s/stats ready before use

    const int wrp  = blockIdx.x * 4 + (tid >> 5);  // 1568*4 = 6272 warps
    const int lane = tid & 31;
    const int qw   = wrp * 8;          // first quad of this warp
    const int ql   = lane & 7;         // loader: local quad
    const int wg   = lane >> 3;        // loader: word group 0..3
    const int q    = qw + ql;
    const int n    = q / 784;
    const int hw   = (q - n * 784) * 4;
    const float* xp = x + (size_t)n * CIN * HW + (size_t)(wg * 64) * HW + hw;

    u64 b0 = 0, b1 = 0, b2 = 0, b3 = 0;
    #pragma unroll 16
    for (int c = 0; c < 64; c++) {
        float4 xv = __ldcs(reinterpret_cast<const float4*>(xp + (size_t)c * HW));
        b0 |= (u64)(xv.x > 0.f) << c;
        b1 |= (u64)(xv.y > 0.f) << c;
        b2 |= (u64)(xv.z > 0.f) << c;
        b3 |= (u64)(xv.w > 0.f) << c;
    }

    const int srcq = lane >> 2;
    const int j    = lane & 3;
    u64 v[4];
    #pragma unroll
    for (int g = 0; g < 4; g++) {
        const int src = g * 8 + srcq;
        u64 t0 = __shfl_sync(0xFFFFFFFFu, b0, src);
        u64 t1 = __shfl_sync(0xFFFFFFFFu, b1, src);
        u64 t2 = __shfl_sync(0xFFFFFFFFu, b2, src);
        u64 t3 = __shfl_sync(0xFFFFFFFFu, b3, src);
        v[g] = (j == 0) ? t0 : (j == 1) ? t1 : (j == 2) ? t2 : t3;
    }
    const u64 v0 = v[0], v1 = v[1], v2 = v[2], v3 = v[3];
    const int p = qw * 4 + lane;       // global pixel

    #pragma unroll 1
    for (int g = 0; g < 8; g++) {
        int pk[4];
        #pragma unroll
        for (int jj = 0; jj < 4; jj++) {
            int sv0 = 0, sv1 = 0;
            #pragma unroll
            for (int k = 0; k < 2; k++) {
                const int co = g * 8 + jj * 2 + k;
                const u64* wq = &w1s[co * 4];
                int d = __popcll(v0 ^ wq[0]) + __popcll(v1 ^ wq[1])
                      + __popcll(v2 ^ wq[2]) + __popcll(v3 ^ wq[3]);
                int s = 256 - 2 * d;
                int rs = __reduce_add_sync(0xFFFFFFFFu, s);
                int rq = __reduce_add_sync(0xFFFFFFFFu, s * s);
                if (lane == 0) { atomicAdd(&ssum[co], rs); atomicAdd(&sss[co], rq); }
                if (k == 0) sv0 = s; else sv1 = s;
            }
            pk[jj] = (sv0 & 0xFFFF) | (sv1 << 16);
        }
        g_s1v[(size_t)g * NPIX + p] = make_int4(pk[0], pk[1], pk[2], pk[3]);
    }
    __syncthreads();
    if (tid < 64) {
        atomicAdd((u64*)&g_sum1[tid], (u64)(long long)ssum[tid]);
        atomicAdd((u64*)&g_ss1[tid],  (u64)(long long)sss[tid]);
    }
}

// ---------------- K2: BN1 threshold -> padded conv2 input bits ----------------
__global__ __launch_bounds__(256) void k2_bnpack1(const float* __restrict__ g1,
                                                  const float* __restrict__ b1) {
    __shared__ float As[64], Bs[64];
    const int tid = threadIdx.x;
    if (tid < 64) {
        double m   = (double)g_sum1[tid] / CNTD;
        double var = (double)g_ss1[tid] / CNTD - m * m;
        double r   = rsqrt(var + EPSD);
        double A   = (double)g1[tid] * r;
        As[tid] = (float)A;
        Bs[tid] = (float)((double)b1[tid] - A * m);
    }
    __syncthreads();
    const int p = blockIdx.x * 256 + tid;
    u64 v = 0;
    #pragma unroll
    for (int g = 0; g < 8; g++) {
        int4 q = g_s1v[(size_t)g * NPIX + p];
        int arr[4] = {q.x, q.y, q.z, q.w};
        #pragma unroll
        for (int k = 0; k < 4; k++) {
            const int co = g * 8 + k * 2;
            float lo = (float)(short)arr[k];
            float hi = (float)(short)(arr[k] >> 16);
            v |= (u64)(fmaf(As[co],     lo, Bs[co])     > 0.f) << co;
            v |= (u64)(fmaf(As[co + 1], hi, Bs[co + 1]) > 0.f) << (co + 1);
        }
    }
    const int n  = p / HW;
    const int hw = p - n * HW;
    const int h  = hw / WW;
    const int w  = hw - h * WW;
    g_a1p[(size_t)n * PADHW + (size_t)(h + 1) * PADW + (w + 1)] = v;
}

// ---------------- K3: conv2 (3x3, pad 1) + stats; 128-thr blocks, smem staging ----------------
__global__ __launch_bounds__(128) void k3_conv2() {
    __shared__ u64 tile[4 * 64];   // 4 padded rows, pitch 64 (58 used)
    __shared__ int bsum[64], bsq[64];
    const int tid  = threadIdx.x;
    const int wid  = tid >> 5;
    const int lane = tid & 31;
    if (tid < 64) { bsum[tid] = 0; bsq[tid] = 0; }

    const int blk = blockIdx.x;          // 1792 = 64 n * 28 row-pairs
    const int n   = blk / 28;
    const int h0  = (blk - n * 28) * 2;  // first output row of this pair

    const u64* src = g_a1p + (size_t)n * PADHW + (size_t)h0 * PADW;
    for (int i = tid; i < 256; i += 128) {
        const int r = i >> 6, c = i & 63;
        if (c < PADW) tile[r * 64 + c] = src[r * PADW + c];
    }
    __syncthreads();

    const int ro   = wid >> 1;           // 0..1: output row within pair
    const int h    = h0 + ro;
    const int half = wid & 1;
    const int ch   = half * 32 + lane;

    const u64 wv0 = g_w2b[ch * 9 + 0], wv1 = g_w2b[ch * 9 + 1], wv2 = g_w2b[ch * 9 + 2];
    const u64 wv3 = g_w2b[ch * 9 + 3], wv4 = g_w2b[ch * 9 + 4], wv5 = g_w2b[ch * 9 + 5];
    const u64 wv6 = g_w2b[ch * 9 + 6], wv7 = g_w2b[ch * 9 + 7], wv8 = g_w2b[ch * 9 + 8];

    const int rowc = (h == 0) ? 1 : ((h == HH - 1) ? 2 : 0);
    const int corr_m = g_ctab[(rowc * 3 + 0) * 64 + ch];
    const int corr_l = g_ctab[(rowc * 3 + 1) * 64 + ch];
    const int corr_r = g_ctab[(rowc * 3 + 2) * 64 + ch];

    const u64* t0 = &tile[ro * 64];
    const u64* t1 = t0 + 64;
    const u64* t2 = t1 + 64;

    short* orow = g_s2 + (size_t)(n * HW + h * WW) * 64 + ch;
    int accs = 0, accq = 0;

    #pragma unroll 1
    for (int c = 0; c < 14; c++) {
        const int base = c * 4;
        #pragma unroll
        for (int j = 0; j < 4; j++) {
            const int w = base + j;
            int d = __popcll(t0[w] ^ wv0) + __popcll(t0[w+1] ^ wv1) + __popcll(t0[w+2] ^ wv2)
                  + __popcll(t1[w] ^ wv3) + __popcll(t1[w+1] ^ wv4) + __popcll(t1[w+2] ^ wv5)
                  + __popcll(t2[w] ^ wv6) + __popcll(t2[w+1] ^ wv7) + __popcll(t2[w+2] ^ wv8);
            const int corr = (w == 0) ? corr_l : ((w == WW - 1) ? corr_r : corr_m);
            int s = 576 - 2 * d - corr;
            accs += s; accq += s * s;
            orow[(size_t)w * 64] = (short)s;
        }
    }

    atomicAdd(&bsum[ch], accs);
    atomicAdd(&bsq[ch],  accq);
    __syncthreads();
    if (tid < 64) {
        atomicAdd((u64*)&g_sum2[tid], (u64)(long long)bsum[tid]);
        atomicAdd((u64*)&g_ss2[tid],  (u64)(long long)bsq[tid]);
    }
}

// ---------------- K4: BN2 threshold -> conv3 bits + ballot transpose ----------------
__global__ __launch_bounds__(256) void k4_pack2(const float* __restrict__ g2,
                                                const float* __restrict__ b2) {
    __shared__ float As[64], Bs[64];
    const int tid = threadIdx.x;
    if (tid < 64) {
        double m   = (double)g_sum2[tid] / CNTD;
        double var = (double)g_ss2[tid] / CNTD - m * m;
        double r   = rsqrt(var + EPSD);
        double A   = (double)g2[tid] * r;
        As[tid] = (float)A;
        Bs[tid] = (float)((double)b2[tid] - A * m);
    }
    __syncthreads();

    const int p = blockIdx.x * 256 + tid;   // 784 blocks
    const int4* sp = reinterpret_cast<const int4*>(g_s2 + (size_t)p * 64);
    u64 v = 0;
    #pragma unroll
    for (int g = 0; g < 8; g++) {
        int4 qq = sp[g];
        int arr[4] = {qq.x, qq.y, qq.z, qq.w};
        #pragma unroll
        for (int k = 0; k < 4; k++) {
            const int co = g * 8 + k * 2;
            float lo = (float)(short)arr[k];
            float hi = (float)(short)(arr[k] >> 16);
            v |= (u64)(fmaf(As[co],     lo, Bs[co])     > 0.f) << co;
            v |= (u64)(fmaf(As[co + 1], hi, Bs[co + 1]) > 0.f) << (co + 1);
        }
    }
    reinterpret_cast<u64*>(g_a2)[p] = v;

    const int lane = tid & 31;
    const int gw   = p >> 5;
    u32 r0 = 0, r1 = 0;
    #pragma unroll
    for (int b = 0; b < 64; b++) {
        u32 bl = __ballot_sync(0xFFFFFFFFu, (u32)((v >> b) & 1ull));
        if (b == lane)      r0 = bl;
        if (b == lane + 32) r1 = bl;
    }
    g_t3[(size_t)gw * 64 + lane]      = r0;
    g_t3[(size_t)gw * 64 + 32 + lane] = r1;
}

// ---------------- K4g: gram matrix of conv3 input bit-columns ----------------
__global__ __launch_bounds__(256) void k4g_gram() {
    __shared__ u32 cw[64][65];   // [word][col]
    const int tid  = threadIdx.x;
    const int base = blockIdx.x * 64;   // 98 blocks * 64 words = NWRD
    for (int e = tid; e < 4096; e += 256) {
        const int w = e >> 6, col = e & 63;
        cw[w][col] = g_t3[(size_t)(base + w) * 64 + col];
    }
    __syncthreads();
    if (tid < 64) {
        int cnt = 0;
        #pragma unroll 8
        for (int w = 0; w < 64; w++) cnt += __popc(cw[w][tid]);
        atomicAdd(&g_n3[tid], cnt);
    }
    for (int e = tid; e < 4096; e += 256) {
        const int i = e >> 6, j = e & 63;
        if (i < j) {
            int d = 0;
            #pragma unroll 8
            for (int w = 0; w < 64; w++) d += __popc(cw[w][i] ^ cw[w][j]);
            atomicAdd(&g_G[e], d);
        }
    }
}

// ---------------- K5: conv3 stats from gram -> FOLDED BN3 affine ----------------
__global__ void k5_fin3(const float* __restrict__ g3, const float* __restrict__ b3) {
    const int c = blockIdx.x;     // 256 blocks x 64 threads
    const int i = threadIdx.x;
    const u64 w = g_w3b[c];
    const int wi = ((int)((w >> i) & 1ull)) * 2 - 1;

    int inner = 0;
    #pragma unroll 8
    for (int j = 0; j < 64; j++) {
        const int wj = ((int)((w >> j) & 1ull)) * 2 - 1;
        int gij;
        if (i == j) gij = NPIX;
        else        gij = NPIX - 2 * g_G[(i < j) ? (i * 64 + j) : (j * 64 + i)];
        inner += wj * gij;
    }
    int c_sq = wi * inner;
    int c_s  = wi * (2 * g_n3[i] - NPIX);

    __shared__ int s_sq[2], s_s[2];
    int rsq = __reduce_add_sync(0xFFFFFFFFu, c_sq);
    int rs  = __reduce_add_sync(0xFFFFFFFFu, c_s);
    if ((i & 31) == 0) { s_sq[i >> 5] = rsq; s_s[i >> 5] = rs; }
    __syncthreads();
    if (i == 0) {
        long long ssq = (long long)s_sq[0] + s_sq[1];
        long long ss  = (long long)s_s[0]  + s_s[1];
        double m   = (double)ss / CNTD;
        double var = (double)ssq / CNTD - m * m;
        double r   = rsqrt(var + EPSD);
        double A   = (double)g3[c] * r;
        double B   = (double)b3[c] - A * m;
        g_A3[c] = (float)(-2.0 * A);
        g_B3[c] = (float)(64.0 * A + B);
    }
}

// ---------------- K6: conv3 recompute + BN3 + residual + hardtanh ----------------
// 2 quads (8 px)/thread: a2 + weights amortized 2x; loads batched 8 at a time.
__global__ __launch_bounds__(256) void k6_final(const float* __restrict__ x,
                                                float* __restrict__ out) {
    __shared__ u64 w3s[8];
    __shared__ float A2s[8], B2s[8];
    const int tid = threadIdx.x;
    const int cg  = blockIdx.y;          // 32 channel groups of 8
    if (tid < 8) {
        w3s[tid] = g_w3b[cg * 8 + tid];
        A2s[tid] = g_A3[cg * 8 + tid];
        B2s[tid] = g_B3[cg * 8 + tid];
    }
    __syncthreads();

    const int qp = blockIdx.x * 256 + tid;   // 98*256 = 25088 = NQUAD/2
    const int n  = qp / 392;
    const int hw = (qp - n * 392) * 8;       // 8 consecutive pixels
    ulonglong4 a0 = g_a2[2 * qp];            // pixels hw..hw+3
    ulonglong4 a1 = g_a2[2 * qp + 1];        // pixels hw+4..hw+7
    const size_t base = ((size_t)n * CIN + (size_t)cg * 8) * HW + hw;

    #pragma unroll
    for (int half = 0; half < 2; half++) {
        float4 xv[8];
        #pragma unroll
        for (int k = 0; k < 4; k++) {
            const size_t off = base + (size_t)(half * 4 + k) * HW;
            xv[2 * k]     = __ldcs(reinterpret_cast<const float4*>(x + off));
            xv[2 * k + 1] = __ldcs(reinterpret_cast<const float4*>(x + off + 4));
        }
        #pragma unroll
        for (int k = 0; k < 4; k++) {
            const int kk = half * 4 + k;
            const u64 wv = w3s[kk];
            const float A = A2s[kk], B = B2s[kk];
            const size_t off = base + (size_t)kk * HW;
            float4 o0, o1;
            o0.x = fminf(fmaxf(fmaf(A, (float)__popcll(a0.x ^ wv), B) + xv[2*k].x, -1.f), 1.f);
            o0.y = fminf(fmaxf(fmaf(A, (float)__popcll(a0.y ^ wv), B) + xv[2*k].y, -1.f), 1.f);
            o0.z = fminf(fmaxf(fmaf(A, (float)__popcll(a0.z ^ wv), B) + xv[2*k].z, -1.f), 1.f);
            o0.w = fminf(fmaxf(fmaf(A, (float)__popcll(a0.w ^ wv), B) + xv[2*k].w, -1.f), 1.f);
            o1.x = fminf(fmaxf(fmaf(A, (float)__popcll(a1.x ^ wv), B) + xv[2*k+1].x, -1.f), 1.f);
            o1.y = fminf(fmaxf(fmaf(A, (float)__popcll(a1.y ^ wv), B) + xv[2*k+1].y, -1.f), 1.f);
            o1.z = fminf(fmaxf(fmaf(A, (float)__popcll(a1.z ^ wv), B) + xv[2*k+1].z, -1.f), 1.f);
            o1.w = fminf(fmaxf(fmaf(A, (float)__popcll(a1.w ^ wv), B) + xv[2*k+1].w, -1.f), 1.f);
            __stcs(reinterpret_cast<float4*>(out + off), o0);
            __stcs(reinterpret_cast<float4*>(out + off + 4), o1);
        }
    }
}

extern "C" void kernel_launch(void* const* d_in, const int* in_sizes, int n_in,
                              void* d_out, int out_size) {
    const float* x  = (const float*)d_in[0];
    const float* w1 = (const float*)d_in[1];
    const float* w2 = (const float*)d_in[2];
    const float* w3 = (const float*)d_in[3];
    const float* g1 = (const float*)d_in[4];
    const float* b1 = (const float*)d_in[5];
    const float* g2 = (const float*)d_in[6];
    const float* b2 = (const float*)d_in[7];
    const float* g3 = (const float*)d_in[8];
    const float* b3 = (const float*)d_in[9];
    float* out = (float*)d_out;

    k0_init<<<64, 64>>>(w1, w2, w3);
    k1_conv1<<<1568, 128>>>(x);
    k2_bnpack1<<<784, 256>>>(g1, b1);
    k3_conv2<<<1792, 128>>>();          // 4th launch -> ncu capture (control)
    k4_pack2<<<784, 256>>>(g2, b2);
    k4g_gram<<<98, 256>>>();
    k5_fin3<<<256, 64>>>(g3, b3);
    dim3 g6(98, 32);
    k6_final<<<g6, 256>>>(x, out);
}

// round 16
// speedup vs baseline: 1.0319x; 1.0319x over previous
#include <cuda_runtime.h>
#include <cstdint>

typedef unsigned long long u64;
typedef unsigned int u32;

#define NB    64
#define CIN   256
#define HH    56
#define WW    56
#define HW    3136
#define NPIX  200704   // NB*HW
#define NQUAD 50176    // NPIX/4
#define NWRD  6272     // NPIX/32
#define CNTD  200704.0
#define EPSD  1e-5
#define PADW  58
#define PADHW 3364     // 58*58

// ---------------- static device scratch ----------------
__device__ u64  g_w1b[64 * 4];
__device__ u64  g_w2b[64 * 9];
__device__ u64  g_w3b[256];
__device__ int  g_ctab[9 * 64];       // border-pattern corrections for conv2
__device__ int4 g_s1v[8 * NPIX];      // conv1 outputs int16, [group][pixel]
__device__ short g_s2[NPIX * 64];     // conv2 outputs int16, [pixel][ch]
__device__ u64  g_a1p[NB * PADHW];    // conv2 input bits, zero halo
__device__ ulonglong4 g_a2[NQUAD];    // conv3 input bits (pixel-major u64)
__device__ u32  g_t3[NWRD * 64];      // transposed conv3 input bits: [pixword][bit]
__device__ int  g_G[4096];            // gram xor-popc, upper triangle i<j
__device__ int  g_n3[64];             // per-bit set counts
__device__ long long g_sum1[64], g_ss1[64];
__device__ long long g_sum2[64], g_ss2[64];
__device__ float g_A3[256], g_B3[256];   // FOLDED: A2 = -2A, B2 = 64A + B

// ---------------- K0: multi-block init; block b owns conv2-channel b ----------------
__global__ __launch_bounds__(64) void k0_init(const float* __restrict__ w1,
                                              const float* __restrict__ w2,
                                              const float* __restrict__ w3) {
    __shared__ float w2s[576];
    __shared__ u64 w2bits[9];
    const int b = blockIdx.x;    // 64 blocks
    const int t = threadIdx.x;   // 64 threads

    for (int i = t; i < 576; i += 64) w2s[i] = w2[b * 576 + i];

    if (t < 4) {
        u64 wd = 0;
        const float* wp = w1 + b * 256 + t * 64;
        #pragma unroll 8
        for (int c = 0; c < 64; c++) wd |= (u64)(wp[c] > 0.f) << c;
        g_w1b[b * 4 + t] = wd;
    }
    if (t >= 4 && t < 8) {
        const int ch = b * 4 + (t - 4);
        u64 wd = 0;
        const float* wp = w3 + ch * 64;
        #pragma unroll 8
        for (int c = 0; c < 64; c++) wd |= (u64)(wp[c] > 0.f) << c;
        g_w3b[ch] = wd;
    }
    g_G[b * 64 + t] = 0;
    if (b == 0) {
        g_sum1[t] = 0; g_ss1[t] = 0;
        g_sum2[t] = 0; g_ss2[t] = 0;
        g_n3[t] = 0;
    }
    __syncthreads();

    if (t < 9) {
        u64 wd = 0;
        #pragma unroll 8
        for (int ci = 0; ci < 64; ci++)
            wd |= (u64)(w2s[ci * 9 + t] > 0.f) << ci;
        g_w2b[b * 9 + t] = wd;
        w2bits[t] = wd;
    }
    __syncthreads();

    if (t < 9) {
        const int rowc = t / 3, colc = t - rowc * 3;
        int corr = 0;
        #pragma unroll
        for (int tap = 0; tap < 9; tap++) {
            const int r = tap / 3, c = tap - r * 3;
            bool inval = (rowc == 1 && r == 0) || (rowc == 2 && r == 2) ||
                         (colc == 1 && c == 0) || (colc == 2 && c == 2);
            if (inval) corr += 64 - 2 * __popcll(w2bits[tap]);
        }
        g_ctab[t * 64 + b] = corr;
    }
}

// ---------------- K1: conv1, warp-synchronous (no phase barrier) ----------------
__global__ __launch_bounds__(128) void k1_conv1(const float* __restrict__ x) {
    __shared__ u64 w1s[256];
    __shared__ int ssum[64], sss[64];
    const int tid = threadIdx.x;
    if (tid < 64) { ssum[tid] = 0; sss[tid] = 0; }
    w1s[tid] = g_w1b[tid];
    w1s[tid + 128] = g_w1b[tid + 128];
    __syncthreads();   // only barrier: w1s/stats ready before use

    const int wrp  = blockIdx.x * 4 + (tid >> 5);  // 1568*4 = 6272 warps
    const int lane = tid & 31;
    const int qw   = wrp * 8;          // first quad of this warp
    const int ql   = lane & 7;         // loader: local quad
    const int wg   = lane >> 3;        // loader: word group 0..3
    const int q    = qw + ql;
    const int n    = q / 784;
    const int hw   = (q - n * 784) * 4;
    const float* xp = x + (size_t)n * CIN * HW + (size_t)(wg * 64) * HW + hw;

    u64 b0 = 0, b1 = 0, b2 = 0, b3 = 0;
    #pragma unroll 16
    for (int c = 0; c < 64; c++) {
        float4 xv = __ldcs(reinterpret_cast<const float4*>(xp + (size_t)c * HW));
        b0 |= (u64)(xv.x > 0.f) << c;
        b1 |= (u64)(xv.y > 0.f) << c;
        b2 |= (u64)(xv.z > 0.f) << c;
        b3 |= (u64)(xv.w > 0.f) << c;
    }

    const int srcq = lane >> 2;
    const int j    = lane & 3;
    u64 v[4];
    #pragma unroll
    for (int g = 0; g < 4; g++) {
        const int src = g * 8 + srcq;
        u64 t0 = __shfl_sync(0xFFFFFFFFu, b0, src);
        u64 t1 = __shfl_sync(0xFFFFFFFFu, b1, src);
        u64 t2 = __shfl_sync(0xFFFFFFFFu, b2, src);
        u64 t3 = __shfl_sync(0xFFFFFFFFu, b3, src);
        v[g] = (j == 0) ? t0 : (j == 1) ? t1 : (j == 2) ? t2 : t3;
    }
    const u64 v0 = v[0], v1 = v[1], v2 = v[2], v3 = v[3];
    const int p = qw * 4 + lane;       // global pixel

    #pragma unroll 1
    for (int g = 0; g < 8; g++) {
        int pk[4];
        #pragma unroll
        for (int jj = 0; jj < 4; jj++) {
            int sv0 = 0, sv1 = 0;
            #pragma unroll
            for (int k = 0; k < 2; k++) {
                const int co = g * 8 + jj * 2 + k;
                const u64* wq = &w1s[co * 4];
                int d = __popcll(v0 ^ wq[0]) + __popcll(v1 ^ wq[1])
                      + __popcll(v2 ^ wq[2]) + __popcll(v3 ^ wq[3]);
                int s = 256 - 2 * d;
                int rs = __reduce_add_sync(0xFFFFFFFFu, s);
                int rq = __reduce_add_sync(0xFFFFFFFFu, s * s);
                if (lane == 0) { atomicAdd(&ssum[co], rs); atomicAdd(&sss[co], rq); }
                if (k == 0) sv0 = s; else sv1 = s;
            }
            pk[jj] = (sv0 & 0xFFFF) | (sv1 << 16);
        }
        g_s1v[(size_t)g * NPIX + p] = make_int4(pk[0], pk[1], pk[2], pk[3]);
    }
    __syncthreads();
    if (tid < 64) {
        atomicAdd((u64*)&g_sum1[tid], (u64)(long long)ssum[tid]);
        atomicAdd((u64*)&g_ss1[tid],  (u64)(long long)sss[tid]);
    }
}

// ---------------- K2: BN1 threshold -> padded conv2 input bits ----------------
__global__ __launch_bounds__(256) void k2_bnpack1(const float* __restrict__ g1,
                                                  const float* __restrict__ b1) {
    __shared__ float As[64], Bs[64];
    const int tid = threadIdx.x;
    if (tid < 64) {
        double m   = (double)g_sum1[tid] / CNTD;
        double var = (double)g_ss1[tid] / CNTD - m * m;
        double r   = rsqrt(var + EPSD);
        double A   = (double)g1[tid] * r;
        As[tid] = (float)A;
        Bs[tid] = (float)((double)b1[tid] - A * m);
    }
    __syncthreads();
    const int p = blockIdx.x * 256 + tid;
    u64 v = 0;
    #pragma unroll
    for (int g = 0; g < 8; g++) {
        int4 q = g_s1v[(size_t)g * NPIX + p];
        int arr[4] = {q.x, q.y, q.z, q.w};
        #pragma unroll
        for (int k = 0; k < 4; k++) {
            const int co = g * 8 + k * 2;
            float lo = (float)(short)arr[k];
            float hi = (float)(short)(arr[k] >> 16);
            v |= (u64)(fmaf(As[co],     lo, Bs[co])     > 0.f) << co;
            v |= (u64)(fmaf(As[co + 1], hi, Bs[co + 1]) > 0.f) << (co + 1);
        }
    }
    const int n  = p / HW;
    const int hw = p - n * HW;
    const int h  = hw / WW;
    const int w  = hw - h * WW;
    g_a1p[(size_t)n * PADHW + (size_t)(h + 1) * PADW + (w + 1)] = v;
}

// ---------------- K3: conv2 (3x3, pad 1) + stats; 128-thr blocks, smem staging ----------------
__global__ __launch_bounds__(128) void k3_conv2() {
    __shared__ u64 tile[4 * 64];   // 4 padded rows, pitch 64 (58 used)
    __shared__ int bsum[64], bsq[64];
    const int tid  = threadIdx.x;
    const int wid  = tid >> 5;
    const int lane = tid & 31;
    if (tid < 64) { bsum[tid] = 0; bsq[tid] = 0; }

    const int blk = blockIdx.x;          // 1792 = 64 n * 28 row-pairs
    const int n   = blk / 28;
    const int h0  = (blk - n * 28) * 2;  // first output row of this pair

    const u64* src = g_a1p + (size_t)n * PADHW + (size_t)h0 * PADW;
    for (int i = tid; i < 256; i += 128) {
        const int r = i >> 6, c = i & 63;
        if (c < PADW) tile[r * 64 + c] = src[r * PADW + c];
    }
    __syncthreads();

    const int ro   = wid >> 1;           // 0..1: output row within pair
    const int h    = h0 + ro;
    const int half = wid & 1;
    const int ch   = half * 32 + lane;

    const u64 wv0 = g_w2b[ch * 9 + 0], wv1 = g_w2b[ch * 9 + 1], wv2 = g_w2b[ch * 9 + 2];
    const u64 wv3 = g_w2b[ch * 9 + 3], wv4 = g_w2b[ch * 9 + 4], wv5 = g_w2b[ch * 9 + 5];
    const u64 wv6 = g_w2b[ch * 9 + 6], wv7 = g_w2b[ch * 9 + 7], wv8 = g_w2b[ch * 9 + 8];

    const int rowc = (h == 0) ? 1 : ((h == HH - 1) ? 2 : 0);
    const int corr_m = g_ctab[(rowc * 3 + 0) * 64 + ch];
    const int corr_l = g_ctab[(rowc * 3 + 1) * 64 + ch];
    const int corr_r = g_ctab[(rowc * 3 + 2) * 64 + ch];

    const u64* t0 = &tile[ro * 64];
    const u64* t1 = t0 + 64;
    const u64* t2 = t1 + 64;

    short* orow = g_s2 + (size_t)(n * HW + h * WW) * 64 + ch;
    int accs = 0, accq = 0;

    #pragma unroll 1
    for (int c = 0; c < 14; c++) {
        const int base = c * 4;
        #pragma unroll
        for (int j = 0; j < 4; j++) {
            const int w = base + j;
            int d = __popcll(t0[w] ^ wv0) + __popcll(t0[w+1] ^ wv1) + __popcll(t0[w+2] ^ wv2)
                  + __popcll(t1[w] ^ wv3) + __popcll(t1[w+1] ^ wv4) + __popcll(t1[w+2] ^ wv5)
                  + __popcll(t2[w] ^ wv6) + __popcll(t2[w+1] ^ wv7) + __popcll(t2[w+2] ^ wv8);
            const int corr = (w == 0) ? corr_l : ((w == WW - 1) ? corr_r : corr_m);
            int s = 576 - 2 * d - corr;
            accs += s; accq += s * s;
            orow[(size_t)w * 64] = (short)s;
        }
    }

    atomicAdd(&bsum[ch], accs);
    atomicAdd(&bsq[ch],  accq);
    __syncthreads();
    if (tid < 64) {
        atomicAdd((u64*)&g_sum2[tid], (u64)(long long)bsum[tid]);
        atomicAdd((u64*)&g_ss2[tid],  (u64)(long long)bsq[tid]);
    }
}

// ---------------- K4: BN2 threshold -> conv3 bits + ballot transpose ----------------
__global__ __launch_bounds__(256) void k4_pack2(const float* __restrict__ g2,
                                                const float* __restrict__ b2) {
    __shared__ float As[64], Bs[64];
    const int tid = threadIdx.x;
    if (tid < 64) {
        double m   = (double)g_sum2[tid] / CNTD;
        double var = (double)g_ss2[tid] / CNTD - m * m;
        double r   = rsqrt(var + EPSD);
        double A   = (double)g2[tid] * r;
        As[tid] = (float)A;
        Bs[tid] = (float)((double)b2[tid] - A * m);
    }
    __syncthreads();

    const int p = blockIdx.x * 256 + tid;   // 784 blocks
    const int4* sp = reinterpret_cast<const int4*>(g_s2 + (size_t)p * 64);
    u64 v = 0;
    #pragma unroll
    for (int g = 0; g < 8; g++) {
        int4 qq = sp[g];
        int arr[4] = {qq.x, qq.y, qq.z, qq.w};
        #pragma unroll
        for (int k = 0; k < 4; k++) {
            const int co = g * 8 + k * 2;
            float lo = (float)(short)arr[k];
            float hi = (float)(short)(arr[k] >> 16);
            v |= (u64)(fmaf(As[co],     lo, Bs[co])     > 0.f) << co;
            v |= (u64)(fmaf(As[co + 1], hi, Bs[co + 1]) > 0.f) << (co + 1);
        }
    }
    reinterpret_cast<u64*>(g_a2)[p] = v;

    const int lane = tid & 31;
    const int gw   = p >> 5;
    u32 r0 = 0, r1 = 0;
    #pragma unroll
    for (int b = 0; b < 64; b++) {
        u32 bl = __ballot_sync(0xFFFFFFFFu, (u32)((v >> b) & 1ull));
        if (b == lane)      r0 = bl;
        if (b == lane + 32) r1 = bl;
    }
    g_t3[(size_t)gw * 64 + lane]      = r0;
    g_t3[(size_t)gw * 64 + 32 + lane] = r1;
}

// ---------------- K4g: gram matrix of conv3 input bit-columns ----------------
__global__ __launch_bounds__(256) void k4g_gram() {
    __shared__ u32 cw[64][65];   // [word][col]
    const int tid  = threadIdx.x;
    const int base = blockIdx.x * 64;   // 98 blocks * 64 words = NWRD
    for (int e = tid; e < 4096; e += 256) {
        const int w = e >> 6, col = e & 63;
        cw[w][col] = g_t3[(size_t)(base + w) * 64 + col];
    }
    __syncthreads();
    if (tid < 64) {
        int cnt = 0;
        #pragma unroll 8
        for (int w = 0; w < 64; w++) cnt += __popc(cw[w][tid]);
        atomicAdd(&g_n3[tid], cnt);
    }
    for (int e = tid; e < 4096; e += 256) {
        const int i = e >> 6, j = e & 63;
        if (i < j) {
            int d = 0;
            #pragma unroll 8
            for (int w = 0; w < 64; w++) d += __popc(cw[w][i] ^ cw[w][j]);
            atomicAdd(&g_G[e], d);
        }
    }
}

// ---------------- K5: conv3 stats from gram -> FOLDED BN3 affine ----------------
__global__ void k5_fin3(const float* __restrict__ g3, const float* __restrict__ b3) {
    const int c = blockIdx.x;     // 256 blocks x 64 threads
    const int i = threadIdx.x;
    const u64 w = g_w3b[c];
    const int wi = ((int)((w >> i) & 1ull)) * 2 - 1;

    int inner = 0;
    #pragma unroll 8
    for (int j = 0; j < 64; j++) {
        const int wj = ((int)((w >> j) & 1ull)) * 2 - 1;
        int gij;
        if (i == j) gij = NPIX;
        else        gij = NPIX - 2 * g_G[(i < j) ? (i * 64 + j) : (j * 64 + i)];
        inner += wj * gij;
    }
    int c_sq = wi * inner;
    int c_s  = wi * (2 * g_n3[i] - NPIX);

    __shared__ int s_sq[2], s_s[2];
    int rsq = __reduce_add_sync(0xFFFFFFFFu, c_sq);
    int rs  = __reduce_add_sync(0xFFFFFFFFu, c_s);
    if ((i & 31) == 0) { s_sq[i >> 5] = rsq; s_s[i >> 5] = rs; }
    __syncthreads();
    if (i == 0) {
        long long ssq = (long long)s_sq[0] + s_sq[1];
        long long ss  = (long long)s_s[0]  + s_s[1];
        double m   = (double)ss / CNTD;
        double var = (double)ssq / CNTD - m * m;
        double r   = rsqrt(var + EPSD);
        double A   = (double)g3[c] * r;
        double B   = (double)b3[c] - A * m;
        g_A3[c] = (float)(-2.0 * A);
        g_B3[c] = (float)(64.0 * A + B);
    }
}

// ---------------- K6: conv3 recompute + BN3 + residual + hardtanh ----------------
// Batched: all 8 x-loads issued before compute (MLP=8/thread); folded affine.
__global__ __launch_bounds__(256) void k6_final(const float* __restrict__ x,
                                                float* __restrict__ out) {
    __shared__ u64 w3s[8];
    __shared__ float A2s[8], B2s[8];
    const int tid = threadIdx.x;
    const int cg  = blockIdx.y;          // 32 channel groups of 8
    if (tid < 8) {
        w3s[tid] = g_w3b[cg * 8 + tid];
        A2s[tid] = g_A3[cg * 8 + tid];
        B2s[tid] = g_B3[cg * 8 + tid];
    }
    __syncthreads();

    const int q  = blockIdx.x * 256 + tid;   // NQUAD
    const int n  = q / 784;
    const int hw = (q - n * 784) * 4;
    ulonglong4 a = g_a2[q];
    const size_t base = ((size_t)n * CIN + (size_t)cg * 8) * HW + hw;

    float4 xv[8];
    #pragma unroll
    for (int k = 0; k < 8; k++)
        xv[k] = __ldcs(reinterpret_cast<const float4*>(x + base + (size_t)k * HW));

    #pragma unroll
    for (int k = 0; k < 8; k++) {
        const u64 wv = w3s[k];
        const float A = A2s[k], B = B2s[k];
        float4 o;
        o.x = fminf(fmaxf(fmaf(A, (float)__popcll(a.x ^ wv), B) + xv[k].x, -1.f), 1.f);
        o.y = fminf(fmaxf(fmaf(A, (float)__popcll(a.y ^ wv), B) + xv[k].y, -1.f), 1.f);
        o.z = fminf(fmaxf(fmaf(A, (float)__popcll(a.z ^ wv), B) + xv[k].z, -1.f), 1.f);
        o.w = fminf(fmaxf(fmaf(A, (float)__popcll(a.w ^ wv), B) + xv[k].w, -1.f), 1.f);
        __stcs(reinterpret_cast<float4*>(out + base + (size_t)k * HW), o);
    }
}

extern "C" void kernel_launch(void* const* d_in, const int* in_sizes, int n_in,
                              void* d_out, int out_size) {
    const float* x  = (const float*)d_in[0];
    const float* w1 = (const float*)d_in[1];
    const float* w2 = (const float*)d_in[2];
    const float* w3 = (const float*)d_in[3];
    const float* g1 = (const float*)d_in[4];
    const float* b1 = (const float*)d_in[5];
    const float* g2 = (const float*)d_in[6];
    const float* b2 = (const float*)d_in[7];
    const float* g3 = (const float*)d_in[8];
    const float* b3 = (const float*)d_in[9];
    float* out = (float*)d_out;

    k0_init<<<64, 64>>>(w1, w2, w3);
    k1_conv1<<<1568, 128>>>(x);
    k2_bnpack1<<<784, 256>>>(g1, b1);
    k3_conv2<<<1792, 128>>>();          // 4th launch -> ncu capture (control)
    k4_pack2<<<784, 256>>>(g2, b2);
    k4g_gram<<<98, 256>>>();
    k5_fin3<<<256, 64>>>(g3, b3);
    dim3 g6(196, 32);
    k6_final<<<g6, 256>>>(x, out);
}